// round 12
// baseline (speedup 1.0000x reference)
#include <cuda_runtime.h>
#include <cstddef>

// ============================================================================
// Problem constants
// ============================================================================
#define NB   8
#define NE   2
#define NG   16
#define NC   8192
#define GMAX 8192
#define NBINS (24*24*2)    // spatial bins, width 25/24 >= max reach of thr
#define NBUK 2048          // sort buckets
#define FINF 3.4028235e38f

static __device__ __constant__ float c_LATX = 0.78125f;
static __device__ __constant__ float c_LATY = 0.78125f;
static __device__ __constant__ float c_LATZ = 0.375f;

// ============================================================================
// Device scratch
// ============================================================================
__device__ float  g_pred [NG][GMAX][4];
__device__ float4 g_ppos4[NG][GMAX];      // x,y,z,|p|^2 (cell order)
__device__ float  g_tgt  [NG][GMAX][4];
__device__ float4 g_tpos4[NG][GMAX];
__device__ int g_Np[NG], g_Nt[NG];

__device__ float  g_spred[NG][GMAX][4];   // sorted ascending by prob
__device__ float4 g_spos4[NG][GMAX];
__device__ int g_restrain[NG][GMAX];
__device__ int g_correct [NG][GMAX];

__device__ float  g_npred[NG][GMAX][4];   // NMS survivors
__device__ float4 g_npos4[NG][GMAX];
__device__ int g_Ns[NG];

// unified S/P spatial bins (same point multiset -> same starts & positions)
__device__ unsigned short g_memP[NG][GMAX];   // cell-order index
__device__ unsigned short g_memS[NG][GMAX];   // sorted rank
__device__ float4 g_binPos[NG][GMAX];
__device__ int g_bsP[NG][NBINS+1];
// N (NMS survivors) and T (targets) bins
__device__ unsigned short g_memN[NG][GMAX], g_memT[NG][GMAX];
__device__ float4 g_binN[NG][GMAX], g_binT[NG][GMAX];
__device__ int g_bsN[NG][NBINS+1], g_bsT[NG][NBINS+1];
__device__ unsigned char g_nzS[NG][GMAX];     // restrain!=0 in slot order

__device__ int g_thas [NG][GMAX], g_targ [NG][GMAX];
__device__ int g_thasn[NG][GMAX], g_targn[NG][GMAX];
__device__ int g_ti[NG][GMAX], g_pi[NG][GMAX];
__device__ int g_tin[NG][GMAX], g_pin[NG][GMAX];
__device__ int g_L[NG], g_Ln[NG];

__device__ float g_thr2[NE];

// ============================================================================
// Rounding-exact helpers (validated rel_err==0.0 across rounds 1-11)
// ============================================================================
__device__ __forceinline__ float nrm3(float x,float y,float z){
    return __fadd_rn(__fadd_rn(__fmul_rn(x,x),__fmul_rn(y,y)),__fmul_rn(z,z));
}
__device__ __forceinline__ float d2_exact(float4 f, float4 q){
    float ab = __fmaf_rn(f.z,q.z,__fmaf_rn(f.y,q.y,__fmul_rn(f.x,q.x)));
    return __fmaf_rn(ab, -2.0f, __fadd_rn(q.w, f.w));
}
__device__ __forceinline__ int binof(float4 p){
    int bx = min((int)(p.x * 0.96f), 23);
    int by = min((int)(p.y * 0.96f), 23);
    int bz = min((int)(p.z * 0.6666667f), 1);
    return (bx*24 + by)*2 + bz;
}

// ============================================================================
// Block-cooperative bin build (blockDim==1024), single member array.
// ============================================================================
__device__ void build_bins_block(const float4* pos, int n, unsigned short* mem,
                                 float4* binpos, int* gstart,
                                 int* bc, int* bs, int* ps){
    int tid = threadIdx.x;
    for (int b = tid; b < NBINS; b += 1024) bc[b] = 0;
    __syncthreads();
    for (int i = tid; i < n; i += 1024) atomicAdd(&bc[binof(pos[i])], 1);
    __syncthreads();
    int c0 = (2*tid   < NBINS) ? bc[2*tid]   : 0;
    int c1 = (2*tid+1 < NBINS) ? bc[2*tid+1] : 0;
    int s = c0 + c1;
    ps[tid] = s; __syncthreads();
    for (int o = 1; o < 1024; o <<= 1){
        int a = (tid >= o) ? ps[tid-o] : 0;
        __syncthreads();
        ps[tid] += a;
        __syncthreads();
    }
    int excl = ps[tid] - s;
    if (2*tid   < NBINS) bs[2*tid]   = excl;
    if (2*tid+1 < NBINS) bs[2*tid+1] = excl + c0;
    if (tid == 0) bs[NBINS] = n;
    __syncthreads();
    for (int b = tid; b < NBINS; b += 1024) bc[b] = bs[b];
    __syncthreads();
    for (int i = tid; i < n; i += 1024){
        float4 p = pos[i];
        int slot = atomicAdd(&bc[binof(p)], 1);
        mem[slot] = (unsigned short)i;
        binpos[slot] = p;
    }
    for (int b = tid; b <= NBINS; b += 1024) gstart[b] = bs[b];
    __syncthreads();
}

// ============================================================================
// k_front: compact + sort + unified S/P bins + T bins. One block of 1024/group.
// ============================================================================
__global__ void __launch_bounds__(1024) k_front(const float* __restrict__ P,
                                                const float* __restrict__ T){
    int g = blockIdx.x, b = g >> 1, e = g & 1, tid = threadIdx.x;
    __shared__ int s_i0[NBUK];            // shp / cnts / bc
    __shared__ int s_i1[NBUK];            // sht / starts / bs
    __shared__ int s_ps[1024];
    __shared__ unsigned short s_mem[GMAX];

    if (g == 0 && tid < NE){
        float diam = (tid==0) ? (float)(0.74*1.4) : (float)(0.528*1.4);
        float d2 = diam*diam;
        unsigned lo = __float_as_uint(d2*0.5f);
        unsigned hi = __float_as_uint(d2*2.0f);
        while (lo + 1u < hi){
            unsigned mid = lo + ((hi - lo) >> 1);
            if (sqrtf(__uint_as_float(mid)) >= diam) hi = mid; else lo = mid;
        }
        g_thr2[tid] = __uint_as_float(hi);
    }

    // ---- compact (8 cells/thread, stable) ----
    float4 pv[8], tv[8];
    unsigned mpm = 0, mtm = 0;
    int cp = 0, ct = 0;
    #pragma unroll
    for (int r = 0; r < 8; r++){
        int c = tid*8 + r;
        size_t idx4 = ((size_t)(b*NC + c))*2 + (size_t)e;
        pv[r] = ((const float4*)P)[idx4];
        tv[r] = ((const float4*)T)[idx4];
        if (pv[r].w > 0.5f){ mpm |= 1u << r; cp++; }
        if (tv[r].w > 0.5f){ mtm |= 1u << r; ct++; }
    }
    s_i0[tid] = cp; s_i1[tid] = ct; __syncthreads();
    for (int o = 1; o < 1024; o <<= 1){
        int a = 0, b2 = 0;
        if (tid >= o){ a = s_i0[tid-o]; b2 = s_i1[tid-o]; }
        __syncthreads();
        s_i0[tid] += a; s_i1[tid] += b2;
        __syncthreads();
    }
    int op = s_i0[tid] - cp, ot = s_i1[tid] - ct;
    int Np = s_i0[1023], Nt = s_i1[1023];
    if (tid == 1023){ g_Np[g] = Np; g_Nt[g] = Nt; }
    #pragma unroll
    for (int r = 0; r < 8; r++){
        int c = tid*8 + r;
        int ci = c >> 8, cj = (c >> 3) & 31, ck = c & 7;
        if ((mpm >> r) & 1u){
            g_pred[g][op][0]=pv[r].x; g_pred[g][op][1]=pv[r].y;
            g_pred[g][op][2]=pv[r].z; g_pred[g][op][3]=pv[r].w;
            float px = __fmul_rn(__fadd_rn(pv[r].x,(float)ci), c_LATX);
            float py = __fmul_rn(__fadd_rn(pv[r].y,(float)cj), c_LATY);
            float pz = __fmul_rn(__fadd_rn(pv[r].z,(float)ck), c_LATZ);
            g_ppos4[g][op] = make_float4(px,py,pz, nrm3(px,py,pz));
            op++;
        }
        if ((mtm >> r) & 1u){
            g_tgt[g][ot][0]=tv[r].x; g_tgt[g][ot][1]=tv[r].y;
            g_tgt[g][ot][2]=tv[r].z; g_tgt[g][ot][3]=tv[r].w;
            float px = __fmul_rn(__fadd_rn(tv[r].x,(float)ci), c_LATX);
            float py = __fmul_rn(__fadd_rn(tv[r].y,(float)cj), c_LATY);
            float pz = __fmul_rn(__fadd_rn(tv[r].z,(float)ck), c_LATZ);
            g_tpos4[g][ot] = make_float4(px,py,pz, nrm3(px,py,pz));
            ot++;
        }
    }
    __syncthreads();

    // ---- stable bucket rank-sort (validated) ----
    s_i0[tid] = 0; s_i0[tid + 1024] = 0;
    __syncthreads();
    for (int i = tid; i < Np; i += 1024){
        float v = g_pred[g][i][3];
        int bb = (int)((v - 0.5f) * 4096.0f);
        bb = min(max(bb, 0), NBUK-1);
        atomicAdd(&s_i0[bb], 1);
    }
    __syncthreads();
    int c0 = s_i0[2*tid], c1 = s_i0[2*tid+1];
    int s = c0 + c1;
    s_ps[tid] = s; __syncthreads();
    for (int o = 1; o < 1024; o <<= 1){
        int a = (tid >= o) ? s_ps[tid-o] : 0;
        __syncthreads();
        s_ps[tid] += a;
        __syncthreads();
    }
    int excl = s_ps[tid] - s;
    s_i1[2*tid]   = excl;
    s_i1[2*tid+1] = excl + c0;
    s_i0[2*tid] = 0; s_i0[2*tid+1] = 0;
    __syncthreads();
    for (int i = tid; i < Np; i += 1024){
        float v = g_pred[g][i][3];
        int bb = (int)((v - 0.5f) * 4096.0f);
        bb = min(max(bb, 0), NBUK-1);
        int slot = s_i1[bb] + atomicAdd(&s_i0[bb], 1);
        s_mem[slot] = (unsigned short)i;
    }
    __syncthreads();
    unsigned short rr[8];
    int nq = 0;
    for (int i = tid; i < Np; i += 1024){
        float v = g_pred[g][i][3];
        int bb = (int)((v - 0.5f) * 4096.0f);
        bb = min(max(bb, 0), NBUK-1);
        int st = s_i1[bb], cn = s_i0[bb];
        int r = 0;
        for (int s2 = 0; s2 < cn; s2++){
            int j = s_mem[st + s2];
            float u = g_pred[g][j][3];
            r += (u < v) || (u == v && j < i);
        }
        int rank = st + r;
        rr[nq++] = (unsigned short)rank;
        g_spred[g][rank][0] = g_pred[g][i][0];
        g_spred[g][rank][1] = g_pred[g][i][1];
        g_spred[g][rank][2] = g_pred[g][i][2];
        g_spred[g][rank][3] = v;
        g_spos4[g][rank] = g_ppos4[g][i];
    }
    __syncthreads();

    // ---- unified S/P bin build (one count/scan; dual member fill) ----
    for (int bb = tid; bb < NBINS; bb += 1024) s_i0[bb] = 0;
    __syncthreads();
    for (int i = tid; i < Np; i += 1024) atomicAdd(&s_i0[binof(g_ppos4[g][i])], 1);
    __syncthreads();
    c0 = (2*tid   < NBINS) ? s_i0[2*tid]   : 0;
    c1 = (2*tid+1 < NBINS) ? s_i0[2*tid+1] : 0;
    s = c0 + c1;
    s_ps[tid] = s; __syncthreads();
    for (int o = 1; o < 1024; o <<= 1){
        int a = (tid >= o) ? s_ps[tid-o] : 0;
        __syncthreads();
        s_ps[tid] += a;
        __syncthreads();
    }
    excl = s_ps[tid] - s;
    if (2*tid   < NBINS) s_i1[2*tid]   = excl;
    if (2*tid+1 < NBINS) s_i1[2*tid+1] = excl + c0;
    if (tid == 0) s_i1[NBINS] = Np;
    __syncthreads();
    for (int bb = tid; bb < NBINS; bb += 1024) s_i0[bb] = s_i1[bb];
    __syncthreads();
    nq = 0;
    for (int i = tid; i < Np; i += 1024){
        float4 p = g_ppos4[g][i];
        int slot = atomicAdd(&s_i0[binof(p)], 1);
        g_memP[g][slot] = (unsigned short)i;
        g_memS[g][slot] = rr[nq++];
        g_binPos[g][slot] = p;
    }
    for (int bb = tid; bb <= NBINS; bb += 1024) g_bsP[g][bb] = s_i1[bb];
    __syncthreads();

    // ---- T bins ----
    build_bins_block(g_tpos4[g], Nt, g_memT[g], g_binT[g], g_bsT[g], s_i0, s_i1, s_ps);
}

// ============================================================================
// k_restrain: 2 adjacent slots per thread (usually same bin -> fused loop).
// grid (32,16) x 128
// ============================================================================
__global__ void __launch_bounds__(128) k_restrain(){
    int g = blockIdx.y;
    int k = blockIdx.x*128 + threadIdx.x;
    int Np = g_Np[g];
    int s0 = 2*k, s1 = 2*k + 1;
    if (s0 >= Np) return;
    bool v1 = s1 < Np;
    float thr = g_thr2[g & 1];
    float4 q0 = g_binPos[g][s0];
    float4 q1 = v1 ? g_binPos[g][s1] : q0;
    int j0 = g_memS[g][s0];
    int j1 = v1 ? g_memS[g][s1] : 0;
    int bx0 = min((int)(q0.x * 0.96f), 23), by0 = min((int)(q0.y * 0.96f), 23);
    int bx1 = min((int)(q1.x * 0.96f), 23), by1 = min((int)(q1.y * 0.96f), 23);
    int c0 = 0, c1 = 0;
    if (v1 && bx0 == bx1 && by0 == by1){
        int ylo = max(by0-1,0), yhi = min(by0+1,23);
        for (int dx = max(bx0-1,0); dx <= min(bx0+1,23); dx++){
            int mlo = g_bsP[g][(dx*24 + ylo)*2];
            int mhi = g_bsP[g][(dx*24 + yhi)*2 + 2];
            for (int m = mlo; m < mhi; m++){
                float4 f = g_binPos[g][m];
                int idx = g_memS[g][m];
                float d20 = d2_exact(f, q0);
                float d21 = d2_exact(f, q1);
                c0 += (idx < j0) && (d20 < thr);
                c1 += (idx < j1) && (d21 < thr);
            }
        }
    } else {
        int ylo = max(by0-1,0), yhi = min(by0+1,23);
        for (int dx = max(bx0-1,0); dx <= min(bx0+1,23); dx++){
            int mlo = g_bsP[g][(dx*24 + ylo)*2];
            int mhi = g_bsP[g][(dx*24 + yhi)*2 + 2];
            for (int m = mlo; m < mhi; m++){
                float4 f = g_binPos[g][m];
                int idx = g_memS[g][m];
                float d2 = d2_exact(f, q0);
                c0 += (idx < j0) && (d2 < thr);
            }
        }
        if (v1){
            ylo = max(by1-1,0); yhi = min(by1+1,23);
            for (int dx = max(bx1-1,0); dx <= min(bx1+1,23); dx++){
                int mlo = g_bsP[g][(dx*24 + ylo)*2];
                int mhi = g_bsP[g][(dx*24 + yhi)*2 + 2];
                for (int m = mlo; m < mhi; m++){
                    float4 f = g_binPos[g][m];
                    int idx = g_memS[g][m];
                    float d2 = d2_exact(f, q1);
                    c1 += (idx < j1) && (d2 < thr);
                }
            }
        }
    }
    g_restrain[g][j0] = c0;
    g_nzS[g][s0] = (c0 != 0);
    if (v1){
        g_restrain[g][j1] = c1;
        g_nzS[g][s1] = (c1 != 0);
    }
}

// ============================================================================
// k_correct: same traversal, counts only nz neighbors.
// ============================================================================
__global__ void __launch_bounds__(128) k_correct(){
    int g = blockIdx.y;
    int k = blockIdx.x*128 + threadIdx.x;
    int Np = g_Np[g];
    int s0 = 2*k, s1 = 2*k + 1;
    if (s0 >= Np) return;
    bool v1 = s1 < Np;
    float thr = g_thr2[g & 1];
    float4 q0 = g_binPos[g][s0];
    float4 q1 = v1 ? g_binPos[g][s1] : q0;
    int j0 = g_memS[g][s0];
    int j1 = v1 ? g_memS[g][s1] : 0;
    int bx0 = min((int)(q0.x * 0.96f), 23), by0 = min((int)(q0.y * 0.96f), 23);
    int bx1 = min((int)(q1.x * 0.96f), 23), by1 = min((int)(q1.y * 0.96f), 23);
    int c0 = 0, c1 = 0;
    if (v1 && bx0 == bx1 && by0 == by1){
        int ylo = max(by0-1,0), yhi = min(by0+1,23);
        for (int dx = max(bx0-1,0); dx <= min(bx0+1,23); dx++){
            int mlo = g_bsP[g][(dx*24 + ylo)*2];
            int mhi = g_bsP[g][(dx*24 + yhi)*2 + 2];
            for (int m = mlo; m < mhi; m++){
                float4 f = g_binPos[g][m];
                int idx = g_memS[g][m];
                int nz = g_nzS[g][m];
                float d20 = d2_exact(f, q0);
                float d21 = d2_exact(f, q1);
                c0 += ((idx < j0) && (d20 < thr)) ? nz : 0;
                c1 += ((idx < j1) && (d21 < thr)) ? nz : 0;
            }
        }
    } else {
        int ylo = max(by0-1,0), yhi = min(by0+1,23);
        for (int dx = max(bx0-1,0); dx <= min(bx0+1,23); dx++){
            int mlo = g_bsP[g][(dx*24 + ylo)*2];
            int mhi = g_bsP[g][(dx*24 + yhi)*2 + 2];
            for (int m = mlo; m < mhi; m++){
                float4 f = g_binPos[g][m];
                int idx = g_memS[g][m];
                float d2 = d2_exact(f, q0);
                c0 += ((idx < j0) && (d2 < thr)) ? (int)g_nzS[g][m] : 0;
            }
        }
        if (v1){
            ylo = max(by1-1,0); yhi = min(by1+1,23);
            for (int dx = max(bx1-1,0); dx <= min(bx1+1,23); dx++){
                int mlo = g_bsP[g][(dx*24 + ylo)*2];
                int mhi = g_bsP[g][(dx*24 + yhi)*2 + 2];
                for (int m = mlo; m < mhi; m++){
                    float4 f = g_binPos[g][m];
                    int idx = g_memS[g][m];
                    float d2 = d2_exact(f, q1);
                    c1 += ((idx < j1) && (d2 < thr)) ? (int)g_nzS[g][m] : 0;
                }
            }
        }
    }
    g_correct[g][j0] = c0;
    if (v1) g_correct[g][j1] = c1;
}

// ============================================================================
// k_nmsc: compact NMS survivors (sel = restrain==correct), stable + N bins
// ============================================================================
__global__ void __launch_bounds__(1024) k_nmsc(){
    int g = blockIdx.x, t = threadIdx.x;
    int Np = g_Np[g];
    __shared__ int sh[1024];
    __shared__ int bc[NBINS];
    __shared__ int bs[NBINS+1];
    __shared__ int ps[1024];
    int cnt = 0;
    #pragma unroll
    for (int r = 0; r < 8; r++){
        int i = t*8 + r;
        if (i < Np && g_restrain[g][i] == g_correct[g][i]) cnt++;
    }
    sh[t] = cnt; __syncthreads();
    for (int o = 1; o < 1024; o <<= 1){
        int a = 0;
        if (t >= o) a = sh[t-o];
        __syncthreads();
        sh[t] += a;
        __syncthreads();
    }
    int off = sh[t] - cnt;
    if (t == 1023) g_Ns[g] = sh[1023];
    #pragma unroll
    for (int r = 0; r < 8; r++){
        int i = t*8 + r;
        if (i < Np && g_restrain[g][i] == g_correct[g][i]){
            #pragma unroll
            for (int c = 0; c < 4; c++) g_npred[g][off][c] = g_spred[g][i][c];
            g_npos4[g][off] = g_spos4[g][i];
            off++;
        }
    }
    __syncthreads();
    int Ns = sh[1023];
    build_bins_block(g_npos4[g], Ns, g_memN[g], g_binN[g], g_bsN[g], bc, bs, ps);
}

// ============================================================================
// k_match: 2 adjacent T-slots per thread (usually same bin -> fused loop).
// grid (32, u=2, 16) x 128
// ============================================================================
__global__ void __launch_bounds__(128) k_match(){
    int g = blockIdx.z, u = blockIdx.y;
    int k = blockIdx.x*128 + threadIdx.x;
    int Nt = g_Nt[g];
    int s0 = 2*k, s1 = 2*k + 1;
    if (s0 >= Nt) return;
    bool v1 = s1 < Nt;
    const float4* bin = u ? g_binN[g] : g_binPos[g];
    const unsigned short* mem = u ? g_memN[g] : g_memP[g];
    const int* bst = u ? g_bsN[g] : g_bsP[g];
    float thr = g_thr2[g & 1];
    float4 q0 = g_binT[g][s0];
    float4 q1 = v1 ? g_binT[g][s1] : q0;
    int t0 = g_memT[g][s0];
    int t1 = v1 ? g_memT[g][s1] : 0;
    int bx0 = min((int)(q0.x * 0.96f), 23), by0 = min((int)(q0.y * 0.96f), 23);
    int bx1 = min((int)(q1.x * 0.96f), 23), by1 = min((int)(q1.y * 0.96f), 23);
    int has0 = 0, arg0 = 0, has1 = 0, arg1 = 0;
    float sm0 = FINF, sm1 = FINF;
    if (v1 && bx0 == bx1 && by0 == by1){
        int ylo = max(by0-1,0), yhi = min(by0+1,23);
        for (int dx = max(bx0-1,0); dx <= min(bx0+1,23); dx++){
            int mlo = bst[(dx*24 + ylo)*2];
            int mhi = bst[(dx*24 + yhi)*2 + 2];
            for (int m = mlo; m < mhi; m++){
                float4 f = bin[m];
                float d20 = d2_exact(f, q0);
                float d21 = d2_exact(f, q1);
                if (d20 < thr){
                    has0 = 1;
                    int idx = mem[m];
                    float sv = sqrtf(fmaxf(d20, 0.0f));
                    if (sv < sm0 || (sv == sm0 && idx < arg0)){ sm0 = sv; arg0 = idx; }
                }
                if (d21 < thr){
                    has1 = 1;
                    int idx = mem[m];
                    float sv = sqrtf(fmaxf(d21, 0.0f));
                    if (sv < sm1 || (sv == sm1 && idx < arg1)){ sm1 = sv; arg1 = idx; }
                }
            }
        }
    } else {
        int ylo = max(by0-1,0), yhi = min(by0+1,23);
        for (int dx = max(bx0-1,0); dx <= min(bx0+1,23); dx++){
            int mlo = bst[(dx*24 + ylo)*2];
            int mhi = bst[(dx*24 + yhi)*2 + 2];
            for (int m = mlo; m < mhi; m++){
                float4 f = bin[m];
                float d2 = d2_exact(f, q0);
                if (d2 < thr){
                    has0 = 1;
                    int idx = mem[m];
                    float sv = sqrtf(fmaxf(d2, 0.0f));
                    if (sv < sm0 || (sv == sm0 && idx < arg0)){ sm0 = sv; arg0 = idx; }
                }
            }
        }
        if (v1){
            ylo = max(by1-1,0); yhi = min(by1+1,23);
            for (int dx = max(bx1-1,0); dx <= min(bx1+1,23); dx++){
                int mlo = bst[(dx*24 + ylo)*2];
                int mhi = bst[(dx*24 + yhi)*2 + 2];
                for (int m = mlo; m < mhi; m++){
                    float4 f = bin[m];
                    float d2 = d2_exact(f, q1);
                    if (d2 < thr){
                        has1 = 1;
                        int idx = mem[m];
                        float sv = sqrtf(fmaxf(d2, 0.0f));
                        if (sv < sm1 || (sv == sm1 && idx < arg1)){ sm1 = sv; arg1 = idx; }
                    }
                }
            }
        }
    }
    if (u){
        g_thasn[g][t0] = has0; g_targn[g][t0] = arg0;
        if (v1){ g_thasn[g][t1] = has1; g_targn[g][t1] = arg1; }
    } else {
        g_thas[g][t0] = has0; g_targ[g][t0] = arg0;
        if (v1){ g_thas[g][t1] = has1; g_targ[g][t1] = arg1; }
    }
}

// ============================================================================
// k_matchc: stable compaction of (ti,pi)/(ti_n,pi_n)
// ============================================================================
__global__ void __launch_bounds__(1024) k_matchc(){
    int g = blockIdx.x, t = threadIdx.x;
    int Nt = g_Nt[g];
    int has0[8], arg0[8], has1[8], arg1[8];
    int c1 = 0, c2 = 0;
    #pragma unroll
    for (int r = 0; r < 8; r++){
        int i = t*8 + r;
        has0[r] = has1[r] = 0; arg0[r] = arg1[r] = 0;
        if (i < Nt){
            has0[r] = g_thas [g][i]; arg0[r] = g_targ [g][i];
            has1[r] = g_thasn[g][i]; arg1[r] = g_targn[g][i];
            c1 += has0[r]; c2 += has1[r];
        }
    }
    __shared__ int s1[1024], s2[1024];
    s1[t] = c1; s2[t] = c2; __syncthreads();
    for (int o = 1; o < 1024; o <<= 1){
        int a = 0, b = 0;
        if (t >= o){ a = s1[t-o]; b = s2[t-o]; }
        __syncthreads();
        s1[t] += a; s2[t] += b;
        __syncthreads();
    }
    int o1 = s1[t] - c1, o2 = s2[t] - c2;
    if (t == 1023){ g_L[g] = s1[1023]; g_Ln[g] = s2[1023]; }
    #pragma unroll
    for (int r = 0; r < 8; r++){
        int i = t*8 + r;
        if (i < Nt){
            if (has0[r]){ g_ti [g][o1] = i; g_pi [g][o1] = arg0[r]; o1++; }
            if (has1[r]){ g_tin[g][o2] = i; g_pin[g][o2] = arg1[r]; o2++; }
        }
    }
}

// ============================================================================
// k_write: one block per (group, array); offsets computed cooperatively.
// ============================================================================
__global__ void __launch_bounds__(256) k_write(float* __restrict__ out){
    int g = blockIdx.x / 10, a = blockIdx.x % 10;
    int tid = threadIdx.x;
    __shared__ int ssz[160];
    __shared__ unsigned long long soff;
    if (tid == 0) soff = 0;
    if (tid < 160){
        int gg = tid / 10, aa = tid % 10;
        int Np = g_Np[gg], Ns = g_Ns[gg], Nt = g_Nt[gg], L = g_L[gg], Ln = g_Ln[gg];
        int sz;
        switch (aa){
            case 0: sz = Np*4; break;
            case 1: sz = Ns*4; break;
            case 2: sz = Nt*4; break;
            case 3: case 4: sz = L; break;
            case 5: case 6: sz = Ln; break;
            case 7: sz = Np*3; break;
            case 8: sz = Ns*3; break;
            default: sz = Nt*3; break;
        }
        ssz[tid] = sz;
    }
    __syncthreads();
    int idx = blockIdx.x;
    unsigned long long part = 0;
    for (int t = tid; t < idx; t += 256) part += (unsigned long long)ssz[t];
    if (part) atomicAdd(&soff, part);
    __syncthreads();
    long long off = (long long)soff;

    int Np = g_Np[g], Ns = g_Ns[g], Nt = g_Nt[g], L = g_L[g], Ln = g_Ln[g];
    int n;
    switch (a){
        case 0: n = Np*4; break;
        case 1: n = Ns*4; break;
        case 2: n = Nt*4; break;
        case 3: case 4: n = L; break;
        case 5: case 6: n = Ln; break;
        case 7: n = Np*3; break;
        case 8: n = Ns*3; break;
        default: n = Nt*3; break;
    }
    const float* pp = (const float*)g_ppos4[g];
    const float* np = (const float*)g_npos4[g];
    const float* tp = (const float*)g_tpos4[g];
    for (int x = tid; x < n; x += 256){
        float v;
        switch (a){
            case 0: v = g_pred [g][x>>2][x&3]; break;
            case 1: v = g_npred[g][x>>2][x&3]; break;
            case 2: v = g_tgt  [g][x>>2][x&3]; break;
            case 3: v = (float)g_ti [g][x]; break;
            case 4: v = (float)g_pi [g][x]; break;
            case 5: v = (float)g_tin[g][x]; break;
            case 6: v = (float)g_pin[g][x]; break;
            case 7: v = pp[(x/3)*4 + x%3]; break;
            case 8: v = np[(x/3)*4 + x%3]; break;
            default:v = tp[(x/3)*4 + x%3]; break;
        }
        out[off + x] = v;
    }
}

// ============================================================================
// Launch
// ============================================================================
extern "C" void kernel_launch(void* const* d_in, const int* in_sizes, int n_in,
                              void* d_out, int out_size){
    const float* P = (const float*)d_in[0];
    const float* T = (const float*)d_in[1];
    float* out = (float*)d_out;
    (void)in_sizes; (void)n_in; (void)out_size;

    k_front   <<<16, 1024>>>(P, T);
    k_restrain<<<dim3(32,16), 128>>>();
    k_correct <<<dim3(32,16), 128>>>();
    k_nmsc    <<<16, 1024>>>();
    k_match   <<<dim3(32,2,16), 128>>>();
    k_matchc  <<<16, 1024>>>();
    k_write   <<<160, 256>>>(out);
}

// round 15
// speedup vs baseline: 1.2386x; 1.2386x over previous
#include <cuda_runtime.h>
#include <cstddef>

// ============================================================================
// Problem constants
// ============================================================================
#define NB   8
#define NE   2
#define NG   16
#define NC   8192
#define GMAX 8192
#define NBINS (24*24*2)    // spatial bins, width 25/24 >= max reach of thr
#define NBUK 2048          // sort buckets
#define FINF 3.4028235e38f

static __device__ __constant__ float c_LATX = 0.78125f;
static __device__ __constant__ float c_LATY = 0.78125f;
static __device__ __constant__ float c_LATZ = 0.375f;

// ============================================================================
// Device scratch
// ============================================================================
__device__ float  g_pred [NG][GMAX][4];
__device__ float4 g_ppos4[NG][GMAX];      // x,y,z,|p|^2 (cell order)
__device__ float  g_tgt  [NG][GMAX][4];
__device__ float4 g_tpos4[NG][GMAX];
__device__ int g_Np[NG], g_Nt[NG];

__device__ float  g_spred[NG][GMAX][4];   // sorted ascending by prob
__device__ float4 g_spos4[NG][GMAX];
__device__ int g_restrain[NG][GMAX];
__device__ int g_correct [NG][GMAX];

__device__ float  g_npred[NG][GMAX][4];   // NMS survivors
__device__ float4 g_npos4[NG][GMAX];
__device__ int g_Ns[NG];

// unified S/P spatial bins (same point multiset -> same starts & positions)
__device__ unsigned short g_memP[NG][GMAX];   // cell-order index
__device__ unsigned short g_memS[NG][GMAX];   // sorted rank
__device__ float4 g_binPos[NG][GMAX];
__device__ int g_bsP[NG][NBINS+1];
// N (NMS survivors) and T (targets) bins
__device__ unsigned short g_memN[NG][GMAX], g_memT[NG][GMAX];
__device__ float4 g_binN[NG][GMAX], g_binT[NG][GMAX];
__device__ int g_bsN[NG][NBINS+1], g_bsT[NG][NBINS+1];
__device__ unsigned char g_nzS[NG][GMAX];     // restrain!=0 in slot order

__device__ int g_thas [NG][GMAX], g_targ [NG][GMAX];
__device__ int g_thasn[NG][GMAX], g_targn[NG][GMAX];
__device__ int g_ti[NG][GMAX], g_pi[NG][GMAX];
__device__ int g_tin[NG][GMAX], g_pin[NG][GMAX];
__device__ int g_L[NG], g_Ln[NG];

__device__ float g_thr2[NE];

// ============================================================================
// Rounding-exact helpers (validated rel_err==0.0 across rounds 1-12)
// ============================================================================
__device__ __forceinline__ float nrm3(float x,float y,float z){
    return __fadd_rn(__fadd_rn(__fmul_rn(x,x),__fmul_rn(y,y)),__fmul_rn(z,z));
}
__device__ __forceinline__ float d2_exact(float4 f, float4 q){
    float ab = __fmaf_rn(f.z,q.z,__fmaf_rn(f.y,q.y,__fmul_rn(f.x,q.x)));
    return __fmaf_rn(ab, -2.0f, __fadd_rn(q.w, f.w));
}
__device__ __forceinline__ int binof(float4 p){
    int bx = min((int)(p.x * 0.96f), 23);
    int by = min((int)(p.y * 0.96f), 23);
    int bz = min((int)(p.z * 0.6666667f), 1);
    return (bx*24 + by)*2 + bz;
}

// ============================================================================
// Block-cooperative bin build (blockDim==1024), single member array.
// ============================================================================
__device__ void build_bins_block(const float4* pos, int n, unsigned short* mem,
                                 float4* binpos, int* gstart,
                                 int* bc, int* bs, int* ps){
    int tid = threadIdx.x;
    for (int b = tid; b < NBINS; b += 1024) bc[b] = 0;
    __syncthreads();
    for (int i = tid; i < n; i += 1024) atomicAdd(&bc[binof(pos[i])], 1);
    __syncthreads();
    int c0 = (2*tid   < NBINS) ? bc[2*tid]   : 0;
    int c1 = (2*tid+1 < NBINS) ? bc[2*tid+1] : 0;
    int s = c0 + c1;
    ps[tid] = s; __syncthreads();
    for (int o = 1; o < 1024; o <<= 1){
        int a = (tid >= o) ? ps[tid-o] : 0;
        __syncthreads();
        ps[tid] += a;
        __syncthreads();
    }
    int excl = ps[tid] - s;
    if (2*tid   < NBINS) bs[2*tid]   = excl;
    if (2*tid+1 < NBINS) bs[2*tid+1] = excl + c0;
    if (tid == 0) bs[NBINS] = n;
    __syncthreads();
    for (int b = tid; b < NBINS; b += 1024) bc[b] = bs[b];
    __syncthreads();
    for (int i = tid; i < n; i += 1024){
        float4 p = pos[i];
        int slot = atomicAdd(&bc[binof(p)], 1);
        mem[slot] = (unsigned short)i;
        binpos[slot] = p;
    }
    for (int b = tid; b <= NBINS; b += 1024) gstart[b] = bs[b];
    __syncthreads();
}

// ============================================================================
// k_compact: fused threshold mask + stable compaction + positions + thr2
// ============================================================================
__global__ void __launch_bounds__(1024) k_compact(const float* __restrict__ P,
                                                  const float* __restrict__ T){
    int g = blockIdx.x, b = g >> 1, e = g & 1, t = threadIdx.x;
    __shared__ int shp[1024], sht[1024];

    if (g == 0 && t < NE){
        float diam = (t==0) ? (float)(0.74*1.4) : (float)(0.528*1.4);
        float d2 = diam*diam;
        unsigned lo = __float_as_uint(d2*0.5f);
        unsigned hi = __float_as_uint(d2*2.0f);
        while (lo + 1u < hi){
            unsigned mid = lo + ((hi - lo) >> 1);
            if (sqrtf(__uint_as_float(mid)) >= diam) hi = mid; else lo = mid;
        }
        g_thr2[t] = __uint_as_float(hi);
    }

    float4 pv[8], tv[8];
    unsigned mpm = 0, mtm = 0;
    int cp = 0, ct = 0;
    #pragma unroll
    for (int r = 0; r < 8; r++){
        int c = t*8 + r;
        size_t idx4 = ((size_t)(b*NC + c))*2 + (size_t)e;
        pv[r] = ((const float4*)P)[idx4];
        tv[r] = ((const float4*)T)[idx4];
        if (pv[r].w > 0.5f){ mpm |= 1u << r; cp++; }
        if (tv[r].w > 0.5f){ mtm |= 1u << r; ct++; }
    }
    shp[t] = cp; sht[t] = ct; __syncthreads();
    for (int o = 1; o < 1024; o <<= 1){
        int a = 0, b2 = 0;
        if (t >= o){ a = shp[t-o]; b2 = sht[t-o]; }
        __syncthreads();
        shp[t] += a; sht[t] += b2;
        __syncthreads();
    }
    int op = shp[t] - cp, ot = sht[t] - ct;
    if (t == 1023){ g_Np[g] = shp[1023]; g_Nt[g] = sht[1023]; }

    #pragma unroll
    for (int r = 0; r < 8; r++){
        int c = t*8 + r;
        int ci = c >> 8, cj = (c >> 3) & 31, ck = c & 7;
        if ((mpm >> r) & 1u){
            g_pred[g][op][0]=pv[r].x; g_pred[g][op][1]=pv[r].y;
            g_pred[g][op][2]=pv[r].z; g_pred[g][op][3]=pv[r].w;
            float px = __fmul_rn(__fadd_rn(pv[r].x,(float)ci), c_LATX);
            float py = __fmul_rn(__fadd_rn(pv[r].y,(float)cj), c_LATY);
            float pz = __fmul_rn(__fadd_rn(pv[r].z,(float)ck), c_LATZ);
            g_ppos4[g][op] = make_float4(px,py,pz, nrm3(px,py,pz));
            op++;
        }
        if ((mtm >> r) & 1u){
            g_tgt[g][ot][0]=tv[r].x; g_tgt[g][ot][1]=tv[r].y;
            g_tgt[g][ot][2]=tv[r].z; g_tgt[g][ot][3]=tv[r].w;
            float px = __fmul_rn(__fadd_rn(tv[r].x,(float)ci), c_LATX);
            float py = __fmul_rn(__fadd_rn(tv[r].y,(float)cj), c_LATY);
            float pz = __fmul_rn(__fadd_rn(tv[r].z,(float)ck), c_LATZ);
            g_tpos4[g][ot] = make_float4(px,py,pz, nrm3(px,py,pz));
            ot++;
        }
    }
}

// ============================================================================
// k_sort: exact stable rank via monotone bucketing (validated), ranks kept
// in registers; then UNIFIED S/P bin build + T bin build.
// ============================================================================
__global__ void __launch_bounds__(1024) k_sort(){
    int g = blockIdx.x;
    int Np = g_Np[g];
    int tid = threadIdx.x;
    __shared__ int s_i0[NBUK];
    __shared__ int s_i1[NBUK];
    __shared__ unsigned short s_mem[GMAX];
    __shared__ int s_ps[1024];

    // ---- bucket rank-sort ----
    s_i0[tid] = 0; s_i0[tid + 1024] = 0;
    __syncthreads();
    for (int i = tid; i < Np; i += 1024){
        float v = g_pred[g][i][3];
        int b = (int)((v - 0.5f) * 4096.0f);
        b = min(max(b, 0), NBUK-1);
        atomicAdd(&s_i0[b], 1);
    }
    __syncthreads();
    int c0 = s_i0[2*tid], c1 = s_i0[2*tid+1];
    int s = c0 + c1;
    s_ps[tid] = s; __syncthreads();
    for (int o = 1; o < 1024; o <<= 1){
        int a = (tid >= o) ? s_ps[tid-o] : 0;
        __syncthreads();
        s_ps[tid] += a;
        __syncthreads();
    }
    int excl = s_ps[tid] - s;
    s_i1[2*tid]   = excl;
    s_i1[2*tid+1] = excl + c0;
    s_i0[2*tid] = 0; s_i0[2*tid+1] = 0;
    __syncthreads();
    for (int i = tid; i < Np; i += 1024){
        float v = g_pred[g][i][3];
        int b = (int)((v - 0.5f) * 4096.0f);
        b = min(max(b, 0), NBUK-1);
        int slot = s_i1[b] + atomicAdd(&s_i0[b], 1);
        s_mem[slot] = (unsigned short)i;
    }
    __syncthreads();
    unsigned short rr[8];
    int nq = 0;
    for (int i = tid; i < Np; i += 1024){
        float v = g_pred[g][i][3];
        int b = (int)((v - 0.5f) * 4096.0f);
        b = min(max(b, 0), NBUK-1);
        int st = s_i1[b], cn = s_i0[b];
        int r = 0;
        for (int s2 = 0; s2 < cn; s2++){
            int j = s_mem[st + s2];
            float u = g_pred[g][j][3];
            r += (u < v) || (u == v && j < i);
        }
        int rank = st + r;
        rr[nq++] = (unsigned short)rank;
        g_spred[g][rank][0] = g_pred[g][i][0];
        g_spred[g][rank][1] = g_pred[g][i][1];
        g_spred[g][rank][2] = g_pred[g][i][2];
        g_spred[g][rank][3] = v;
        g_spos4[g][rank] = g_ppos4[g][i];
    }
    __syncthreads();

    // ---- unified S/P bin build ----
    for (int b = tid; b < NBINS; b += 1024) s_i0[b] = 0;
    __syncthreads();
    for (int i = tid; i < Np; i += 1024) atomicAdd(&s_i0[binof(g_ppos4[g][i])], 1);
    __syncthreads();
    c0 = (2*tid   < NBINS) ? s_i0[2*tid]   : 0;
    c1 = (2*tid+1 < NBINS) ? s_i0[2*tid+1] : 0;
    s = c0 + c1;
    s_ps[tid] = s; __syncthreads();
    for (int o = 1; o < 1024; o <<= 1){
        int a = (tid >= o) ? s_ps[tid-o] : 0;
        __syncthreads();
        s_ps[tid] += a;
        __syncthreads();
    }
    excl = s_ps[tid] - s;
    if (2*tid   < NBINS) s_i1[2*tid]   = excl;
    if (2*tid+1 < NBINS) s_i1[2*tid+1] = excl + c0;
    if (tid == 0) s_i1[NBINS] = Np;
    __syncthreads();
    for (int b = tid; b < NBINS; b += 1024) s_i0[b] = s_i1[b];
    __syncthreads();
    nq = 0;
    for (int i = tid; i < Np; i += 1024){
        float4 p = g_ppos4[g][i];
        int slot = atomicAdd(&s_i0[binof(p)], 1);
        g_memP[g][slot] = (unsigned short)i;
        g_memS[g][slot] = rr[nq++];
        g_binPos[g][slot] = p;
    }
    for (int b = tid; b <= NBINS; b += 1024) g_bsP[g][b] = s_i1[b];
    __syncthreads();

    // ---- T bins ----
    build_bins_block(g_tpos4[g], g_Nt[g], g_memT[g], g_binT[g], g_bsT[g],
                     s_i0, s_i1, s_ps);
}

// ============================================================================
// k_restrain: one thread per bin slot (warp-coherent; R11-validated shape).
// ============================================================================
__global__ void __launch_bounds__(256) k_restrain(){
    int g = blockIdx.y;
    int s = blockIdx.x*256 + threadIdx.x;
    int Np = g_Np[g];
    if (s >= Np) return;
    float thr = g_thr2[g & 1];
    float4 q = g_binPos[g][s];
    int j = g_memS[g][s];
    int bx = min((int)(q.x * 0.96f), 23);
    int by = min((int)(q.y * 0.96f), 23);
    int ylo = max(by-1,0), yhi = min(by+1,23);
    int cnt = 0;
    for (int dx = max(bx-1,0); dx <= min(bx+1,23); dx++){
        int mlo = g_bsP[g][(dx*24 + ylo)*2];
        int mhi = g_bsP[g][(dx*24 + yhi)*2 + 2];
        for (int m = mlo; m < mhi; m++){
            float4 f = g_binPos[g][m];
            float d2 = d2_exact(f, q);
            int idx = g_memS[g][m];
            cnt += (idx < j) && (d2 < thr);
        }
    }
    g_restrain[g][j] = cnt;
    g_nzS[g][s] = (cnt != 0);
}

// ============================================================================
// k_correct: same traversal; nz read in slot order.
// ============================================================================
__global__ void __launch_bounds__(256) k_correct(){
    int g = blockIdx.y;
    int s = blockIdx.x*256 + threadIdx.x;
    int Np = g_Np[g];
    if (s >= Np) return;
    float thr = g_thr2[g & 1];
    float4 q = g_binPos[g][s];
    int j = g_memS[g][s];
    int bx = min((int)(q.x * 0.96f), 23);
    int by = min((int)(q.y * 0.96f), 23);
    int ylo = max(by-1,0), yhi = min(by+1,23);
    int cnt = 0;
    for (int dx = max(bx-1,0); dx <= min(bx+1,23); dx++){
        int mlo = g_bsP[g][(dx*24 + ylo)*2];
        int mhi = g_bsP[g][(dx*24 + yhi)*2 + 2];
        for (int m = mlo; m < mhi; m++){
            float4 f = g_binPos[g][m];
            float d2 = d2_exact(f, q);
            int idx = g_memS[g][m];
            cnt += ((idx < j) && (d2 < thr)) ? (int)g_nzS[g][m] : 0;
        }
    }
    g_correct[g][j] = cnt;
}

// ============================================================================
// k_nmsc: compact NMS survivors (sel = restrain==correct), stable + N bins
// ============================================================================
__global__ void __launch_bounds__(1024) k_nmsc(){
    int g = blockIdx.x, t = threadIdx.x;
    int Np = g_Np[g];
    __shared__ int sh[1024];
    __shared__ int bc[NBINS];
    __shared__ int bs[NBINS+1];
    __shared__ int ps[1024];
    int cnt = 0;
    #pragma unroll
    for (int r = 0; r < 8; r++){
        int i = t*8 + r;
        if (i < Np && g_restrain[g][i] == g_correct[g][i]) cnt++;
    }
    sh[t] = cnt; __syncthreads();
    for (int o = 1; o < 1024; o <<= 1){
        int a = 0;
        if (t >= o) a = sh[t-o];
        __syncthreads();
        sh[t] += a;
        __syncthreads();
    }
    int off = sh[t] - cnt;
    if (t == 1023) g_Ns[g] = sh[1023];
    #pragma unroll
    for (int r = 0; r < 8; r++){
        int i = t*8 + r;
        if (i < Np && g_restrain[g][i] == g_correct[g][i]){
            #pragma unroll
            for (int c = 0; c < 4; c++) g_npred[g][off][c] = g_spred[g][i][c];
            g_npos4[g][off] = g_spos4[g][i];
            off++;
        }
    }
    __syncthreads();
    int Ns = sh[1023];
    build_bins_block(g_npos4[g], Ns, g_memN[g], g_binN[g], g_bsN[g], bc, bs, ps);
}

// ============================================================================
// k_match: one thread per T-bin slot (R11-validated shape).
// u=0: unified P view (binPos/memP/bsP); u=1: N bins.
// ============================================================================
__global__ void __launch_bounds__(256) k_match(){
    int g = blockIdx.z, u = blockIdx.y;
    int s = blockIdx.x*256 + threadIdx.x;
    int Nt = g_Nt[g];
    if (s >= Nt) return;
    const float4* bin = u ? g_binN[g] : g_binPos[g];
    const unsigned short* mem = u ? g_memN[g] : g_memP[g];
    const int* bst = u ? g_bsN[g] : g_bsP[g];
    float thr = g_thr2[g & 1];
    float4 q = g_binT[g][s];
    int t = g_memT[g][s];
    int bx = min((int)(q.x * 0.96f), 23);
    int by = min((int)(q.y * 0.96f), 23);
    int ylo = max(by-1,0), yhi = min(by+1,23);
    int has = 0, arg = 0;
    float smin = FINF;
    for (int dx = max(bx-1,0); dx <= min(bx+1,23); dx++){
        int mlo = bst[(dx*24 + ylo)*2];
        int mhi = bst[(dx*24 + yhi)*2 + 2];
        for (int m = mlo; m < mhi; m++){
            float4 f = bin[m];
            float d2 = d2_exact(f, q);
            if (d2 < thr){
                has = 1;
                int idx = mem[m];
                float sv = sqrtf(fmaxf(d2, 0.0f));
                if (sv < smin || (sv == smin && idx < arg)){ smin = sv; arg = idx; }
            }
        }
    }
    if (u){ g_thasn[g][t] = has; g_targn[g][t] = arg; }
    else  { g_thas [g][t] = has; g_targ [g][t] = arg; }
}

// ============================================================================
// k_matchc: stable compaction of (ti,pi)/(ti_n,pi_n)
// ============================================================================
__global__ void __launch_bounds__(1024) k_matchc(){
    int g = blockIdx.x, t = threadIdx.x;
    int Nt = g_Nt[g];
    int has0[8], arg0[8], has1[8], arg1[8];
    int c1 = 0, c2 = 0;
    #pragma unroll
    for (int r = 0; r < 8; r++){
        int i = t*8 + r;
        has0[r] = has1[r] = 0; arg0[r] = arg1[r] = 0;
        if (i < Nt){
            has0[r] = g_thas [g][i]; arg0[r] = g_targ [g][i];
            has1[r] = g_thasn[g][i]; arg1[r] = g_targn[g][i];
            c1 += has0[r]; c2 += has1[r];
        }
    }
    __shared__ int s1[1024], s2[1024];
    s1[t] = c1; s2[t] = c2; __syncthreads();
    for (int o = 1; o < 1024; o <<= 1){
        int a = 0, b = 0;
        if (t >= o){ a = s1[t-o]; b = s2[t-o]; }
        __syncthreads();
        s1[t] += a; s2[t] += b;
        __syncthreads();
    }
    int o1 = s1[t] - c1, o2 = s2[t] - c2;
    if (t == 1023){ g_L[g] = s1[1023]; g_Ln[g] = s2[1023]; }
    #pragma unroll
    for (int r = 0; r < 8; r++){
        int i = t*8 + r;
        if (i < Nt){
            if (has0[r]){ g_ti [g][o1] = i; g_pi [g][o1] = arg0[r]; o1++; }
            if (has1[r]){ g_tin[g][o2] = i; g_pin[g][o2] = arg1[r]; o2++; }
        }
    }
}

// ============================================================================
// k_write: one block per (group, array); offsets computed cooperatively
// (32-bit shared atomic; total output elements < 2^31).
// ============================================================================
__global__ void __launch_bounds__(256) k_write(float* __restrict__ out){
    int g = blockIdx.x / 10, a = blockIdx.x % 10;
    int tid = threadIdx.x;
    __shared__ int ssz[160];
    __shared__ unsigned soff;
    if (tid == 0) soff = 0u;
    if (tid < 160){
        int gg = tid / 10, aa = tid % 10;
        int Np = g_Np[gg], Ns = g_Ns[gg], Nt = g_Nt[gg], L = g_L[gg], Ln = g_Ln[gg];
        int sz;
        switch (aa){
            case 0: sz = Np*4; break;
            case 1: sz = Ns*4; break;
            case 2: sz = Nt*4; break;
            case 3: case 4: sz = L; break;
            case 5: case 6: sz = Ln; break;
            case 7: sz = Np*3; break;
            case 8: sz = Ns*3; break;
            default: sz = Nt*3; break;
        }
        ssz[tid] = sz;
    }
    __syncthreads();
    int idx = blockIdx.x;
    unsigned part = 0;
    for (int t = tid; t < idx; t += 256) part += (unsigned)ssz[t];
    if (part) atomicAdd(&soff, part);
    __syncthreads();
    long long off = (long long)soff;

    int Np = g_Np[g], Ns = g_Ns[g], Nt = g_Nt[g], L = g_L[g], Ln = g_Ln[g];
    int n;
    switch (a){
        case 0: n = Np*4; break;
        case 1: n = Ns*4; break;
        case 2: n = Nt*4; break;
        case 3: case 4: n = L; break;
        case 5: case 6: n = Ln; break;
        case 7: n = Np*3; break;
        case 8: n = Ns*3; break;
        default: n = Nt*3; break;
    }
    const float* pp = (const float*)g_ppos4[g];
    const float* np = (const float*)g_npos4[g];
    const float* tp = (const float*)g_tpos4[g];
    for (int x = tid; x < n; x += 256){
        float v;
        switch (a){
            case 0: v = g_pred [g][x>>2][x&3]; break;
            case 1: v = g_npred[g][x>>2][x&3]; break;
            case 2: v = g_tgt  [g][x>>2][x&3]; break;
            case 3: v = (float)g_ti [g][x]; break;
            case 4: v = (float)g_pi [g][x]; break;
            case 5: v = (float)g_tin[g][x]; break;
            case 6: v = (float)g_pin[g][x]; break;
            case 7: v = pp[(x/3)*4 + x%3]; break;
            case 8: v = np[(x/3)*4 + x%3]; break;
            default:v = tp[(x/3)*4 + x%3]; break;
        }
        out[off + x] = v;
    }
}

// ============================================================================
// Launch
// ============================================================================
extern "C" void kernel_launch(void* const* d_in, const int* in_sizes, int n_in,
                              void* d_out, int out_size){
    const float* P = (const float*)d_in[0];
    const float* T = (const float*)d_in[1];
    float* out = (float*)d_out;
    (void)in_sizes; (void)n_in; (void)out_size;

    k_compact <<<16, 1024>>>(P, T);
    k_sort    <<<16, 1024>>>();
    k_restrain<<<dim3(32,16), 256>>>();
    k_correct <<<dim3(32,16), 256>>>();
    k_nmsc    <<<16, 1024>>>();
    k_match   <<<dim3(32,2,16), 256>>>();
    k_matchc  <<<16, 1024>>>();
    k_write   <<<160, 256>>>(out);
}

// round 16
// speedup vs baseline: 1.2540x; 1.0124x over previous
#include <cuda_runtime.h>
#include <cstddef>

// ============================================================================
// Problem constants
// ============================================================================
#define NB   8
#define NE   2
#define NG   16
#define NC   8192
#define GMAX 8192
#define NBINS (24*24*2)    // spatial bins, width 25/24 >= max reach of thr
#define NBUK 2048          // sort buckets
#define FINF 3.4028235e38f

static __device__ __constant__ float c_LATX = 0.78125f;
static __device__ __constant__ float c_LATY = 0.78125f;
static __device__ __constant__ float c_LATZ = 0.375f;

// ============================================================================
// Device scratch
// ============================================================================
__device__ float  g_pred [NG][GMAX][4];
__device__ float4 g_ppos4[NG][GMAX];      // x,y,z,|p|^2 (cell order)
__device__ float  g_tgt  [NG][GMAX][4];
__device__ float4 g_tpos4[NG][GMAX];
__device__ int g_Np[NG], g_Nt[NG];

__device__ float  g_spred[NG][GMAX][4];   // sorted ascending by prob
__device__ float4 g_spos4[NG][GMAX];
__device__ int g_restrain[NG][GMAX];
__device__ int g_correct [NG][GMAX];

__device__ float  g_npred[NG][GMAX][4];   // NMS survivors
__device__ float4 g_npos4[NG][GMAX];
__device__ int g_Ns[NG];

// unified S/P spatial bins (same point multiset -> same starts & positions)
__device__ unsigned short g_memP[NG][GMAX];   // cell-order index
__device__ unsigned short g_memS[NG][GMAX];   // sorted rank
__device__ float4 g_binPos[NG][GMAX];
__device__ int g_bsP[NG][NBINS+1];
// N (NMS survivors) and T (targets) bins
__device__ unsigned short g_memN[NG][GMAX], g_memT[NG][GMAX];
__device__ float4 g_binN[NG][GMAX], g_binT[NG][GMAX];
__device__ int g_bsN[NG][NBINS+1], g_bsT[NG][NBINS+1];
__device__ unsigned char g_nzS[NG][GMAX];     // restrain!=0 in slot order

__device__ int g_thas [NG][GMAX], g_targ [NG][GMAX];
__device__ int g_thasn[NG][GMAX], g_targn[NG][GMAX];
__device__ int g_ti[NG][GMAX], g_pi[NG][GMAX];
__device__ int g_tin[NG][GMAX], g_pin[NG][GMAX];
__device__ int g_L[NG], g_Ln[NG];

__device__ float g_thr2[NE];

// ============================================================================
// Rounding-exact helpers (validated rel_err==0.0 across rounds 1-15)
// ============================================================================
__device__ __forceinline__ float nrm3(float x,float y,float z){
    return __fadd_rn(__fadd_rn(__fmul_rn(x,x),__fmul_rn(y,y)),__fmul_rn(z,z));
}
__device__ __forceinline__ float d2_exact(float4 f, float4 q){
    float ab = __fmaf_rn(f.z,q.z,__fmaf_rn(f.y,q.y,__fmul_rn(f.x,q.x)));
    return __fmaf_rn(ab, -2.0f, __fadd_rn(q.w, f.w));
}
__device__ __forceinline__ int binof(float4 p){
    int bx = min((int)(p.x * 0.96f), 23);
    int by = min((int)(p.y * 0.96f), 23);
    int bz = min((int)(p.z * 0.6666667f), 1);
    return (bx*24 + by)*2 + bz;
}

// ============================================================================
// Inclusive block scan over 1024 threads via warp shuffles (3 barriers).
// Exact integer prefix sums (associativity exact). ws: shared int[32].
// ============================================================================
__device__ __forceinline__ int scan1024_inc(int v, int* ws){
    int lane = threadIdx.x & 31, w = threadIdx.x >> 5;
    #pragma unroll
    for (int o = 1; o < 32; o <<= 1){
        int n = __shfl_up_sync(0xffffffffu, v, o);
        if (lane >= o) v += n;
    }
    if (lane == 31) ws[w] = v;
    __syncthreads();
    if (w == 0){
        int s = ws[lane];
        #pragma unroll
        for (int o = 1; o < 32; o <<= 1){
            int n = __shfl_up_sync(0xffffffffu, s, o);
            if (lane >= o) s += n;
        }
        ws[lane] = s;
    }
    __syncthreads();
    int r = v + ((w > 0) ? ws[w-1] : 0);
    __syncthreads();   // ws reusable by caller afterwards
    return r;
}

// ============================================================================
// Block-cooperative bin build (blockDim==1024), single member array.
// ============================================================================
__device__ void build_bins_block(const float4* pos, int n, unsigned short* mem,
                                 float4* binpos, int* gstart,
                                 int* bc, int* bs, int* ws){
    int tid = threadIdx.x;
    for (int b = tid; b < NBINS; b += 1024) bc[b] = 0;
    __syncthreads();
    for (int i = tid; i < n; i += 1024) atomicAdd(&bc[binof(pos[i])], 1);
    __syncthreads();
    int c0 = (2*tid   < NBINS) ? bc[2*tid]   : 0;
    int c1 = (2*tid+1 < NBINS) ? bc[2*tid+1] : 0;
    int s = c0 + c1;
    int incl = scan1024_inc(s, ws);
    int excl = incl - s;
    if (2*tid   < NBINS) bs[2*tid]   = excl;
    if (2*tid+1 < NBINS) bs[2*tid+1] = excl + c0;
    if (tid == 0) bs[NBINS] = n;
    __syncthreads();
    for (int b = tid; b < NBINS; b += 1024) bc[b] = bs[b];
    __syncthreads();
    for (int i = tid; i < n; i += 1024){
        float4 p = pos[i];
        int slot = atomicAdd(&bc[binof(p)], 1);
        mem[slot] = (unsigned short)i;
        binpos[slot] = p;
    }
    for (int b = tid; b <= NBINS; b += 1024) gstart[b] = bs[b];
    __syncthreads();
}

// ============================================================================
// k_compact: fused threshold mask + stable compaction + positions + thr2
// ============================================================================
__global__ void __launch_bounds__(1024) k_compact(const float* __restrict__ P,
                                                  const float* __restrict__ T){
    int g = blockIdx.x, b = g >> 1, e = g & 1, t = threadIdx.x;
    __shared__ int ws[32];

    if (g == 0 && t < NE){
        float diam = (t==0) ? (float)(0.74*1.4) : (float)(0.528*1.4);
        float d2 = diam*diam;
        unsigned lo = __float_as_uint(d2*0.5f);
        unsigned hi = __float_as_uint(d2*2.0f);
        while (lo + 1u < hi){
            unsigned mid = lo + ((hi - lo) >> 1);
            if (sqrtf(__uint_as_float(mid)) >= diam) hi = mid; else lo = mid;
        }
        g_thr2[t] = __uint_as_float(hi);
    }

    float4 pv[8], tv[8];
    unsigned mpm = 0, mtm = 0;
    int cp = 0, ct = 0;
    #pragma unroll
    for (int r = 0; r < 8; r++){
        int c = t*8 + r;
        size_t idx4 = ((size_t)(b*NC + c))*2 + (size_t)e;
        pv[r] = ((const float4*)P)[idx4];
        tv[r] = ((const float4*)T)[idx4];
        if (pv[r].w > 0.5f){ mpm |= 1u << r; cp++; }
        if (tv[r].w > 0.5f){ mtm |= 1u << r; ct++; }
    }
    int ip = scan1024_inc(cp, ws);
    int it = scan1024_inc(ct, ws);
    int op = ip - cp, ot = it - ct;
    if (t == 1023){ g_Np[g] = ip; g_Nt[g] = it; }

    #pragma unroll
    for (int r = 0; r < 8; r++){
        int c = t*8 + r;
        int ci = c >> 8, cj = (c >> 3) & 31, ck = c & 7;
        if ((mpm >> r) & 1u){
            g_pred[g][op][0]=pv[r].x; g_pred[g][op][1]=pv[r].y;
            g_pred[g][op][2]=pv[r].z; g_pred[g][op][3]=pv[r].w;
            float px = __fmul_rn(__fadd_rn(pv[r].x,(float)ci), c_LATX);
            float py = __fmul_rn(__fadd_rn(pv[r].y,(float)cj), c_LATY);
            float pz = __fmul_rn(__fadd_rn(pv[r].z,(float)ck), c_LATZ);
            g_ppos4[g][op] = make_float4(px,py,pz, nrm3(px,py,pz));
            op++;
        }
        if ((mtm >> r) & 1u){
            g_tgt[g][ot][0]=tv[r].x; g_tgt[g][ot][1]=tv[r].y;
            g_tgt[g][ot][2]=tv[r].z; g_tgt[g][ot][3]=tv[r].w;
            float px = __fmul_rn(__fadd_rn(tv[r].x,(float)ci), c_LATX);
            float py = __fmul_rn(__fadd_rn(tv[r].y,(float)cj), c_LATY);
            float pz = __fmul_rn(__fadd_rn(tv[r].z,(float)ck), c_LATZ);
            g_tpos4[g][ot] = make_float4(px,py,pz, nrm3(px,py,pz));
            ot++;
        }
    }
}

// ============================================================================
// k_sort: exact stable rank via monotone bucketing (validated), ranks kept
// in registers; then UNIFIED S/P bin build + T bin build.
// ============================================================================
__global__ void __launch_bounds__(1024) k_sort(){
    int g = blockIdx.x;
    int Np = g_Np[g];
    int tid = threadIdx.x;
    __shared__ int s_i0[NBUK];
    __shared__ int s_i1[NBUK];
    __shared__ unsigned short s_mem[GMAX];
    __shared__ int ws[32];

    // ---- bucket rank-sort ----
    s_i0[tid] = 0; s_i0[tid + 1024] = 0;
    __syncthreads();
    for (int i = tid; i < Np; i += 1024){
        float v = g_pred[g][i][3];
        int b = (int)((v - 0.5f) * 4096.0f);
        b = min(max(b, 0), NBUK-1);
        atomicAdd(&s_i0[b], 1);
    }
    __syncthreads();
    int c0 = s_i0[2*tid], c1 = s_i0[2*tid+1];
    int s = c0 + c1;
    int incl = scan1024_inc(s, ws);
    int excl = incl - s;
    s_i1[2*tid]   = excl;
    s_i1[2*tid+1] = excl + c0;
    s_i0[2*tid] = 0; s_i0[2*tid+1] = 0;
    __syncthreads();
    for (int i = tid; i < Np; i += 1024){
        float v = g_pred[g][i][3];
        int b = (int)((v - 0.5f) * 4096.0f);
        b = min(max(b, 0), NBUK-1);
        int slot = s_i1[b] + atomicAdd(&s_i0[b], 1);
        s_mem[slot] = (unsigned short)i;
    }
    __syncthreads();
    unsigned short rr[8];
    int nq = 0;
    for (int i = tid; i < Np; i += 1024){
        float v = g_pred[g][i][3];
        int b = (int)((v - 0.5f) * 4096.0f);
        b = min(max(b, 0), NBUK-1);
        int st = s_i1[b], cn = s_i0[b];
        int r = 0;
        for (int s2 = 0; s2 < cn; s2++){
            int j = s_mem[st + s2];
            float u = g_pred[g][j][3];
            r += (u < v) || (u == v && j < i);
        }
        int rank = st + r;
        rr[nq++] = (unsigned short)rank;
        g_spred[g][rank][0] = g_pred[g][i][0];
        g_spred[g][rank][1] = g_pred[g][i][1];
        g_spred[g][rank][2] = g_pred[g][i][2];
        g_spred[g][rank][3] = v;
        g_spos4[g][rank] = g_ppos4[g][i];
    }
    __syncthreads();

    // ---- unified S/P bin build ----
    for (int b = tid; b < NBINS; b += 1024) s_i0[b] = 0;
    __syncthreads();
    for (int i = tid; i < Np; i += 1024) atomicAdd(&s_i0[binof(g_ppos4[g][i])], 1);
    __syncthreads();
    c0 = (2*tid   < NBINS) ? s_i0[2*tid]   : 0;
    c1 = (2*tid+1 < NBINS) ? s_i0[2*tid+1] : 0;
    s = c0 + c1;
    incl = scan1024_inc(s, ws);
    excl = incl - s;
    if (2*tid   < NBINS) s_i1[2*tid]   = excl;
    if (2*tid+1 < NBINS) s_i1[2*tid+1] = excl + c0;
    if (tid == 0) s_i1[NBINS] = Np;
    __syncthreads();
    for (int b = tid; b < NBINS; b += 1024) s_i0[b] = s_i1[b];
    __syncthreads();
    nq = 0;
    for (int i = tid; i < Np; i += 1024){
        float4 p = g_ppos4[g][i];
        int slot = atomicAdd(&s_i0[binof(p)], 1);
        g_memP[g][slot] = (unsigned short)i;
        g_memS[g][slot] = rr[nq++];
        g_binPos[g][slot] = p;
    }
    for (int b = tid; b <= NBINS; b += 1024) g_bsP[g][b] = s_i1[b];
    __syncthreads();

    // ---- T bins ----
    build_bins_block(g_tpos4[g], g_Nt[g], g_memT[g], g_binT[g], g_bsT[g],
                     s_i0, s_i1, ws);
}

// ============================================================================
// k_pairA: role-fused launch. y==0: restrain (writes restrain[j], nzS[slot]).
// y==1: match u=0 against unified P bins (independent of restrain).
// Both latency-bound -> co-residency fills stalls. grid (32, 2, 16), 256 thr.
// ============================================================================
__global__ void __launch_bounds__(256) k_pairA(){
    int g = blockIdx.z;
    int s = blockIdx.x*256 + threadIdx.x;
    float thr = g_thr2[g & 1];
    if (blockIdx.y == 0){
        int Np = g_Np[g];
        if (s >= Np) return;
        float4 q = g_binPos[g][s];
        int j = g_memS[g][s];
        int bx = min((int)(q.x * 0.96f), 23);
        int by = min((int)(q.y * 0.96f), 23);
        int ylo = max(by-1,0), yhi = min(by+1,23);
        int cnt = 0;
        for (int dx = max(bx-1,0); dx <= min(bx+1,23); dx++){
            int mlo = g_bsP[g][(dx*24 + ylo)*2];
            int mhi = g_bsP[g][(dx*24 + yhi)*2 + 2];
            for (int m = mlo; m < mhi; m++){
                float4 f = g_binPos[g][m];
                float d2 = d2_exact(f, q);
                int idx = g_memS[g][m];
                cnt += (idx < j) && (d2 < thr);
            }
        }
        g_restrain[g][j] = cnt;
        g_nzS[g][s] = (cnt != 0);
    } else {
        int Nt = g_Nt[g];
        if (s >= Nt) return;
        float4 q = g_binT[g][s];
        int t = g_memT[g][s];
        int bx = min((int)(q.x * 0.96f), 23);
        int by = min((int)(q.y * 0.96f), 23);
        int ylo = max(by-1,0), yhi = min(by+1,23);
        int has = 0, arg = 0;
        float smin = FINF;
        for (int dx = max(bx-1,0); dx <= min(bx+1,23); dx++){
            int mlo = g_bsP[g][(dx*24 + ylo)*2];
            int mhi = g_bsP[g][(dx*24 + yhi)*2 + 2];
            for (int m = mlo; m < mhi; m++){
                float4 f = g_binPos[g][m];
                float d2 = d2_exact(f, q);
                if (d2 < thr){
                    has = 1;
                    int idx = g_memP[g][m];
                    float sv = sqrtf(fmaxf(d2, 0.0f));
                    if (sv < smin || (sv == smin && idx < arg)){ smin = sv; arg = idx; }
                }
            }
        }
        g_thas[g][t] = has; g_targ[g][t] = arg;
    }
}

// ============================================================================
// k_correct: same traversal as restrain; nz read in slot order.
// ============================================================================
__global__ void __launch_bounds__(256) k_correct(){
    int g = blockIdx.y;
    int s = blockIdx.x*256 + threadIdx.x;
    int Np = g_Np[g];
    if (s >= Np) return;
    float thr = g_thr2[g & 1];
    float4 q = g_binPos[g][s];
    int j = g_memS[g][s];
    int bx = min((int)(q.x * 0.96f), 23);
    int by = min((int)(q.y * 0.96f), 23);
    int ylo = max(by-1,0), yhi = min(by+1,23);
    int cnt = 0;
    for (int dx = max(bx-1,0); dx <= min(bx+1,23); dx++){
        int mlo = g_bsP[g][(dx*24 + ylo)*2];
        int mhi = g_bsP[g][(dx*24 + yhi)*2 + 2];
        for (int m = mlo; m < mhi; m++){
            float4 f = g_binPos[g][m];
            float d2 = d2_exact(f, q);
            int idx = g_memS[g][m];
            cnt += ((idx < j) && (d2 < thr)) ? (int)g_nzS[g][m] : 0;
        }
    }
    g_correct[g][j] = cnt;
}

// ============================================================================
// k_nmsc: compact NMS survivors (sel = restrain==correct), stable + N bins
// ============================================================================
__global__ void __launch_bounds__(1024) k_nmsc(){
    int g = blockIdx.x, t = threadIdx.x;
    int Np = g_Np[g];
    __shared__ int bc[NBINS];
    __shared__ int bs[NBINS+1];
    __shared__ int ws[32];
    __shared__ int sNs;
    int cnt = 0;
    int sel[8];
    #pragma unroll
    for (int r = 0; r < 8; r++){
        int i = t*8 + r;
        sel[r] = (i < Np && g_restrain[g][i] == g_correct[g][i]);
        cnt += sel[r];
    }
    int incl = scan1024_inc(cnt, ws);
    int off = incl - cnt;
    if (t == 1023){ g_Ns[g] = incl; sNs = incl; }
    #pragma unroll
    for (int r = 0; r < 8; r++){
        int i = t*8 + r;
        if (sel[r]){
            #pragma unroll
            for (int c = 0; c < 4; c++) g_npred[g][off][c] = g_spred[g][i][c];
            g_npos4[g][off] = g_spos4[g][i];
            off++;
        }
    }
    __syncthreads();
    build_bins_block(g_npos4[g], sNs, g_memN[g], g_binN[g], g_bsN[g], bc, bs, ws);
}

// ============================================================================
// k_match1: match u=1 (against N bins). grid (32,16), 256 thr.
// ============================================================================
__global__ void __launch_bounds__(256) k_match1(){
    int g = blockIdx.y;
    int s = blockIdx.x*256 + threadIdx.x;
    int Nt = g_Nt[g];
    if (s >= Nt) return;
    float thr = g_thr2[g & 1];
    float4 q = g_binT[g][s];
    int t = g_memT[g][s];
    int bx = min((int)(q.x * 0.96f), 23);
    int by = min((int)(q.y * 0.96f), 23);
    int ylo = max(by-1,0), yhi = min(by+1,23);
    int has = 0, arg = 0;
    float smin = FINF;
    for (int dx = max(bx-1,0); dx <= min(bx+1,23); dx++){
        int mlo = g_bsN[g][(dx*24 + ylo)*2];
        int mhi = g_bsN[g][(dx*24 + yhi)*2 + 2];
        for (int m = mlo; m < mhi; m++){
            float4 f = g_binN[g][m];
            float d2 = d2_exact(f, q);
            if (d2 < thr){
                has = 1;
                int idx = g_memN[g][m];
                float sv = sqrtf(fmaxf(d2, 0.0f));
                if (sv < smin || (sv == smin && idx < arg)){ smin = sv; arg = idx; }
            }
        }
    }
    g_thasn[g][t] = has; g_targn[g][t] = arg;
}

// ============================================================================
// k_matchc: stable compaction of (ti,pi)/(ti_n,pi_n)
// ============================================================================
__global__ void __launch_bounds__(1024) k_matchc(){
    int g = blockIdx.x, t = threadIdx.x;
    int Nt = g_Nt[g];
    __shared__ int ws[32];
    int has0[8], arg0[8], has1[8], arg1[8];
    int c1 = 0, c2 = 0;
    #pragma unroll
    for (int r = 0; r < 8; r++){
        int i = t*8 + r;
        has0[r] = has1[r] = 0; arg0[r] = arg1[r] = 0;
        if (i < Nt){
            has0[r] = g_thas [g][i]; arg0[r] = g_targ [g][i];
            has1[r] = g_thasn[g][i]; arg1[r] = g_targn[g][i];
            c1 += has0[r]; c2 += has1[r];
        }
    }
    int i1 = scan1024_inc(c1, ws);
    int i2 = scan1024_inc(c2, ws);
    int o1 = i1 - c1, o2 = i2 - c2;
    if (t == 1023){ g_L[g] = i1; g_Ln[g] = i2; }
    #pragma unroll
    for (int r = 0; r < 8; r++){
        int i = t*8 + r;
        if (i < Nt){
            if (has0[r]){ g_ti [g][o1] = i; g_pi [g][o1] = arg0[r]; o1++; }
            if (has1[r]){ g_tin[g][o2] = i; g_pin[g][o2] = arg1[r]; o2++; }
        }
    }
}

// ============================================================================
// k_write: one block per (group, array); offsets computed cooperatively
// (32-bit shared atomic; total output elements < 2^31).
// ============================================================================
__global__ void __launch_bounds__(256) k_write(float* __restrict__ out){
    int g = blockIdx.x / 10, a = blockIdx.x % 10;
    int tid = threadIdx.x;
    __shared__ int ssz[160];
    __shared__ unsigned soff;
    if (tid == 0) soff = 0u;
    if (tid < 160){
        int gg = tid / 10, aa = tid % 10;
        int Np = g_Np[gg], Ns = g_Ns[gg], Nt = g_Nt[gg], L = g_L[gg], Ln = g_Ln[gg];
        int sz;
        switch (aa){
            case 0: sz = Np*4; break;
            case 1: sz = Ns*4; break;
            case 2: sz = Nt*4; break;
            case 3: case 4: sz = L; break;
            case 5: case 6: sz = Ln; break;
            case 7: sz = Np*3; break;
            case 8: sz = Ns*3; break;
            default: sz = Nt*3; break;
        }
        ssz[tid] = sz;
    }
    __syncthreads();
    int idx = blockIdx.x;
    unsigned part = 0;
    for (int t = tid; t < idx; t += 256) part += (unsigned)ssz[t];
    if (part) atomicAdd(&soff, part);
    __syncthreads();
    long long off = (long long)soff;

    int Np = g_Np[g], Ns = g_Ns[g], Nt = g_Nt[g], L = g_L[g], Ln = g_Ln[g];
    int n;
    switch (a){
        case 0: n = Np*4; break;
        case 1: n = Ns*4; break;
        case 2: n = Nt*4; break;
        case 3: case 4: n = L; break;
        case 5: case 6: n = Ln; break;
        case 7: n = Np*3; break;
        case 8: n = Ns*3; break;
        default: n = Nt*3; break;
    }
    const float* pp = (const float*)g_ppos4[g];
    const float* np = (const float*)g_npos4[g];
    const float* tp = (const float*)g_tpos4[g];
    for (int x = tid; x < n; x += 256){
        float v;
        switch (a){
            case 0: v = g_pred [g][x>>2][x&3]; break;
            case 1: v = g_npred[g][x>>2][x&3]; break;
            case 2: v = g_tgt  [g][x>>2][x&3]; break;
            case 3: v = (float)g_ti [g][x]; break;
            case 4: v = (float)g_pi [g][x]; break;
            case 5: v = (float)g_tin[g][x]; break;
            case 6: v = (float)g_pin[g][x]; break;
            case 7: v = pp[(x/3)*4 + x%3]; break;
            case 8: v = np[(x/3)*4 + x%3]; break;
            default:v = tp[(x/3)*4 + x%3]; break;
        }
        out[off + x] = v;
    }
}

// ============================================================================
// Launch
// ============================================================================
extern "C" void kernel_launch(void* const* d_in, const int* in_sizes, int n_in,
                              void* d_out, int out_size){
    const float* P = (const float*)d_in[0];
    const float* T = (const float*)d_in[1];
    float* out = (float*)d_out;
    (void)in_sizes; (void)n_in; (void)out_size;

    k_compact <<<16, 1024>>>(P, T);
    k_sort    <<<16, 1024>>>();
    k_pairA   <<<dim3(32,2,16), 256>>>();   // restrain + match(u=0) overlapped
    k_correct <<<dim3(32,16), 256>>>();
    k_nmsc    <<<16, 1024>>>();
    k_match1  <<<dim3(32,16), 256>>>();
    k_matchc  <<<16, 1024>>>();
    k_write   <<<160, 256>>>(out);
}